// round 13
// baseline (speedup 1.0000x reference)
#include <cuda_runtime.h>
#include <cstdint>

#define Bz 4
#define S 1024
#define D 768
#define H 12
#define DK 64
#define BH (Bz*H)

// ---------------- scratch (device globals) ----------------
__device__ float g_Q[Bz*S*D];
__device__ float g_K[Bz*S*D];
__device__ float g_QT[BH*DK*S];
__device__ float g_KT[BH*DK*S];
__device__ float g_P[(size_t)BH*S*S];      // P[bh][t][s] = exp(score), 0 if masked (fp32)
__device__ float g_ctx[2*Bz*S*D];          // ctx1 | ctx2
__device__ float g_t[2*Bz*S*D];
__device__ float g_cpart[(size_t)BH*64*S]; // per-(block,warp) partial col sums
__device__ float g_rinv[BH*S];             // 1/sum_t P  (per s)  -> ctx1
__device__ float g_cinv[BH*S];             // 1/sum_s P  (per t)  -> ctx2
__device__ int   g_mask_mode;              // 0=i32, 1=u8, 2=f32

// ---------------- helpers ----------------
__device__ __forceinline__ unsigned tf32c(float x) {
    unsigned u; asm("cvt.rna.tf32.f32 %0, %1;" : "=r"(u) : "f"(x)); return u;
}
__device__ __forceinline__ void mma8(float c[4], const unsigned a[4], const unsigned b[2]) {
    asm volatile(
        "mma.sync.aligned.m16n8k8.row.col.f32.tf32.tf32.f32 "
        "{%0,%1,%2,%3},{%4,%5,%6,%7},{%8,%9},{%0,%1,%2,%3};\n"
        : "+f"(c[0]), "+f"(c[1]), "+f"(c[2]), "+f"(c[3])
        : "r"(a[0]), "r"(a[1]), "r"(a[2]), "r"(a[3]), "r"(b[0]), "r"(b[1]));
}
__device__ __forceinline__ int kperm(int k) {  // within-chunk k (0..31) -> permuted slot
    return (k & ~7) + 2 * (k & 3) + ((k & 7) >> 2);
}

// ---------------- mask dtype sniffer ----------------
__global__ void detect_mask_kernel(const unsigned int* __restrict__ w) {
    __shared__ int s01, sf;
    if (threadIdx.x == 0) { s01 = 1; sf = 1; }
    __syncthreads();
    int a01 = 1, af = 1;
    for (int i = threadIdx.x; i < 4096; i += 256) {
        unsigned v = w[i];
        if (v != 0u && v != 1u) a01 = 0;
        if (v != 0u && v != 0x3F800000u) af = 0;
    }
    if (!a01) atomicAnd(&s01, 0);
    if (!af)  atomicAnd(&sf, 0);
    __syncthreads();
    if (threadIdx.x == 0) g_mask_mode = s01 ? 0 : (sf ? 2 : 1);
}

// ---------------- tf32 GEMM 128x128x32 body (R2/R9 exact) ----------------
__device__ __forceinline__ void mm128_body(const float* __restrict__ A,
                                           const float* __restrict__ B,
                                           float* __restrict__ C,
                                           int m0, int n0,
                                           unsigned* As, unsigned* Bs) {
    const int tid = threadIdx.x, lane = tid & 31, w = tid >> 5;
    const int g = lane >> 2, tq = lane & 3;
    const int mw = (w & 1) * 64, nw = (w >> 1) * 32;
    float c[16][4] = {};
    for (int k0 = 0; k0 < 768; k0 += 32) {
        {   // A: 128x32
            int kq = tid & 7, kc = kq * 4, bkp = (kq >> 1) * 8 + (kq & 1);
            #pragma unroll
            for (int it = 0; it < 4; it++) {
                int m = (tid >> 3) + it * 32;
                float4 v = *(const float4*)(A + (size_t)(m0 + m) * 768 + k0 + kc);
                unsigned* dst = &As[m * 36 + bkp];
                dst[0] = tf32c(v.x); dst[2] = tf32c(v.y); dst[4] = tf32c(v.z); dst[6] = tf32c(v.w);
            }
        }
        {   // B: 32x128 (row-major k x n)
            #pragma unroll
            for (int it = 0; it < 4; it++) {
                int kr = (tid >> 5) + it * 8;
                int nc = lane * 4;
                float4 v = *(const float4*)(B + (size_t)(k0 + kr) * 768 + n0 + nc);
                uint4 u; u.x = tf32c(v.x); u.y = tf32c(v.y); u.z = tf32c(v.z); u.w = tf32c(v.w);
                *(uint4*)&Bs[kperm(kr) * 132 + nc] = u;
            }
        }
        __syncthreads();
        #pragma unroll
        for (int ks = 0; ks < 4; ks++) {
            unsigned a[4][4], bf[4][2];
            #pragma unroll
            for (int i = 0; i < 4; i++) {
                int r = mw + 16 * i + g;
                uint2 x = *(const uint2*)&As[r * 36 + ks * 8 + 2 * tq];
                uint2 y = *(const uint2*)&As[(r + 8) * 36 + ks * 8 + 2 * tq];
                a[i][0] = x.x; a[i][1] = y.x; a[i][2] = x.y; a[i][3] = y.y;
            }
            #pragma unroll
            for (int j = 0; j < 4; j++) {
                int col = nw + 8 * j + g;
                bf[j][0] = Bs[(ks * 8 + 2 * tq) * 132 + col];
                bf[j][1] = Bs[(ks * 8 + 2 * tq + 1) * 132 + col];
            }
            #pragma unroll
            for (int i = 0; i < 4; i++)
                #pragma unroll
                for (int j = 0; j < 4; j++) mma8(c[i * 4 + j], a[i], bf[j]);
        }
        __syncthreads();
    }
    #pragma unroll
    for (int i = 0; i < 4; i++) {
        int r = m0 + mw + 16 * i + g;
        #pragma unroll
        for (int j = 0; j < 4; j++) {
            int col = n0 + nw + 8 * j + 2 * tq;
            *(float2*)(C + (size_t)r * 768 + col)       = make_float2(c[i*4+j][0], c[i*4+j][1]);
            *(float2*)(C + (size_t)(r + 8) * 768 + col) = make_float2(c[i*4+j][2], c[i*4+j][3]);
        }
    }
}

// merged Q/K projection: z=0 -> A1@B1->C1, z=1 -> A2@B2->C2
__global__ void __launch_bounds__(256, 2) mm128_dual_kernel(const float* __restrict__ A1,
                                                            const float* __restrict__ B1,
                                                            float* __restrict__ C1,
                                                            const float* __restrict__ A2,
                                                            const float* __restrict__ B2,
                                                            float* __restrict__ C2) {
    __shared__ unsigned As[128 * 36];
    __shared__ unsigned Bs[32 * 132];
    const int m0 = blockIdx.y * 128, n0 = blockIdx.x * 128;
    if (blockIdx.z == 0) mm128_body(A1, B1, C1, m0, n0, As, Bs);
    else                 mm128_body(A2, B2, C2, m0, n0, As, Bs);
}

// single GEMM (output projection)
__global__ void __launch_bounds__(256, 2) mm128_kernel(const float* __restrict__ A,
                                                       const float* __restrict__ B,
                                                       float* __restrict__ C) {
    __shared__ unsigned As[128 * 36];
    __shared__ unsigned Bs[32 * 132];
    mm128_body(A, B, C, blockIdx.y * 128, blockIdx.x * 128, As, Bs);
}

// ---------------- head transpose, merged Q/K: z in [0, 2*BH) ----------------
__global__ void tr_kernel(const float* __restrict__ Qm, float* __restrict__ QT,
                          const float* __restrict__ Km, float* __restrict__ KT) {
    __shared__ float tile[32][33];
    int z = blockIdx.z;
    const float* X = (z < BH) ? Qm : Km;
    float* XT = (z < BH) ? QT : KT;
    int bh = (z < BH) ? z : z - BH;
    int b = bh / H, h = bh % H;
    int s0 = blockIdx.x * 32, d0 = blockIdx.y * 32;
    int tx = threadIdx.x, ty = threadIdx.y;
    #pragma unroll
    for (int i = 0; i < 4; i++)
        tile[ty + 8 * i][tx] = X[(size_t)(b * S + s0 + ty + 8 * i) * D + h * DK + d0 + tx];
    __syncthreads();
    #pragma unroll
    for (int i = 0; i < 4; i++)
        XT[(size_t)(bh * DK + d0 + ty + 8 * i) * S + s0 + tx] = tile[tx][ty + 8 * i];
}

// ---------------- scoresT -> P[bh][t][s] = exp((K_t.Q_s)/8), 0 if masked ----------------
__global__ void __launch_bounds__(256, 2) scoresT_kernel(const float* __restrict__ Kmat,
                                                         const float* __restrict__ QT,
                                                         const void* __restrict__ mask,
                                                         float* __restrict__ P) {
    __shared__ unsigned As[128 * 36];
    __shared__ unsigned Bs[32 * 132];
    const int bh = blockIdx.z, b = bh / H, h = bh % H;
    const int s0 = blockIdx.x * 128, t0 = blockIdx.y * 128;
    const float* Ag = Kmat + (size_t)(b * S + t0) * D + h * DK;
    const float* Bg = QT + (size_t)bh * DK * S + s0;
    const int tid = threadIdx.x, lane = tid & 31, w = tid >> 5;
    const int g = lane >> 2, tq = lane & 3;
    const int mw = (w & 1) * 64, nw = (w >> 1) * 32;
    float c[16][4] = {};
    #pragma unroll
    for (int k0 = 0; k0 < 64; k0 += 32) {
        {
            int kq = tid & 7, kc = kq * 4, bkp = (kq >> 1) * 8 + (kq & 1);
            #pragma unroll
            for (int it = 0; it < 4; it++) {
                int m = (tid >> 3) + it * 32;
                float4 v = *(const float4*)(Ag + (size_t)m * D + k0 + kc);
                unsigned* dst = &As[m * 36 + bkp];
                dst[0] = tf32c(v.x); dst[2] = tf32c(v.y); dst[4] = tf32c(v.z); dst[6] = tf32c(v.w);
            }
        }
        {
            #pragma unroll
            for (int it = 0; it < 4; it++) {
                int kr = (tid >> 5) + it * 8;
                int nc = lane * 4;
                float4 v = *(const float4*)(Bg + (size_t)(k0 + kr) * S + nc);
                uint4 u; u.x = tf32c(v.x); u.y = tf32c(v.y); u.z = tf32c(v.z); u.w = tf32c(v.w);
                *(uint4*)&Bs[kperm(kr) * 132 + nc] = u;
            }
        }
        __syncthreads();
        #pragma unroll
        for (int ks = 0; ks < 4; ks++) {
            unsigned a[4][4], bf[4][2];
            #pragma unroll
            for (int i = 0; i < 4; i++) {
                int r = mw + 16 * i + g;
                uint2 x = *(const uint2*)&As[r * 36 + ks * 8 + 2 * tq];
                uint2 y = *(const uint2*)&As[(r + 8) * 36 + ks * 8 + 2 * tq];
                a[i][0] = x.x; a[i][1] = y.x; a[i][2] = x.y; a[i][3] = y.y;
            }
            #pragma unroll
            for (int j = 0; j < 4; j++) {
                int col = nw + 8 * j + g;
                bf[j][0] = Bs[(ks * 8 + 2 * tq) * 132 + col];
                bf[j][1] = Bs[(ks * 8 + 2 * tq + 1) * 132 + col];
            }
            #pragma unroll
            for (int i = 0; i < 4; i++)
                #pragma unroll
                for (int j = 0; j < 4; j++) mma8(c[i * 4 + j], a[i], bf[j]);
        }
        __syncthreads();
    }
    const int mode = g_mask_mode;
    const int* m32 = (const int*)mask;
    const unsigned char* m8 = (const unsigned char*)mask;
    const float* mf = (const float*)mask;
    #pragma unroll
    for (int i = 0; i < 4; i++) {
        int rA = t0 + mw + 16 * i + g;
        #pragma unroll
        for (int j = 0; j < 4; j++) {
            int cs = s0 + nw + 8 * j + 2 * tq;
            float* cc = c[i * 4 + j];
            size_t iA = ((size_t)bh * S + rA) * S + cs;
            size_t iB = iA + (size_t)8 * S;
            bool k0m, k1m, k2m, k3m;
            if (mode == 0) {
                int2 qa = *(const int2*)(m32 + iA); int2 qb = *(const int2*)(m32 + iB);
                k0m = qa.x != 0; k1m = qa.y != 0; k2m = qb.x != 0; k3m = qb.y != 0;
            } else if (mode == 1) {
                uchar2 qa = *(const uchar2*)(m8 + iA); uchar2 qb = *(const uchar2*)(m8 + iB);
                k0m = qa.x != 0; k1m = qa.y != 0; k2m = qb.x != 0; k3m = qb.y != 0;
            } else {
                float2 qa = *(const float2*)(mf + iA); float2 qb = *(const float2*)(mf + iB);
                k0m = qa.x != 0.0f; k1m = qa.y != 0.0f; k2m = qb.x != 0.0f; k3m = qb.y != 0.0f;
            }
            float2 o0, o1;
            o0.x = k0m ? 0.0f : __expf(0.125f * cc[0]);
            o0.y = k1m ? 0.0f : __expf(0.125f * cc[1]);
            o1.x = k2m ? 0.0f : __expf(0.125f * cc[2]);
            o1.y = k3m ? 0.0f : __expf(0.125f * cc[3]);
            *(float2*)(P + iA) = o0;
            *(float2*)(P + iB) = o1;
        }
    }
}

// ---------------- fused dual sums over fp32 P (no expf) ----------------
__global__ void __launch_bounds__(256) sums_kernel(const float* __restrict__ Pm,
                                                   float* __restrict__ cpart,
                                                   float* __restrict__ cinv) {
    int bh = blockIdx.y, blk = blockIdx.x;
    int w = threadIdx.x >> 5, lane = threadIdx.x & 31;
    int t0 = blk * 128 + w * 16;
    float colacc[8][4] = {};
    const float* base = Pm + ((size_t)bh * S + t0) * S;
    for (int r = 0; r < 16; r++) {
        const float* row = base + (size_t)r * S;
        float rsum = 0.f;
        #pragma unroll
        for (int k = 0; k < 8; k++) {
            float4 v = *(const float4*)(row + k * 128 + lane * 4);
            colacc[k][0] += v.x; colacc[k][1] += v.y;
            colacc[k][2] += v.z; colacc[k][3] += v.w;
            rsum += (v.x + v.y) + (v.z + v.w);
        }
        #pragma unroll
        for (int o = 16; o; o >>= 1) rsum += __shfl_xor_sync(0xffffffffu, rsum, o);
        if (lane == 0) cinv[bh * S + t0 + r] = 1.0f / rsum;
    }
    float* cp = cpart + ((size_t)bh * 64 + blk * 8 + w) * S;
    #pragma unroll
    for (int k = 0; k < 8; k++)
        *(float4*)(cp + k * 128 + lane * 4) =
            make_float4(colacc[k][0], colacc[k][1], colacc[k][2], colacc[k][3]);
}

__global__ void rinv_kernel(const float* __restrict__ cpart, float* __restrict__ rinv) {
    int bh = blockIdx.y;
    int s = blockIdx.x * 256 + threadIdx.x;
    const float* p = cpart + (size_t)bh * 64 * S + s;
    float sum = 0.f;
    #pragma unroll
    for (int j = 0; j < 64; j++) sum += p[(size_t)j * S];
    rinv[bh * S + s] = 1.0f / sum;
}

// ---------------- merged ctx: z=0 -> ctx1, z=1 -> ctx2 (P input; inv in epilogue) ----------------
__global__ void __launch_bounds__(256, 2) ctx_kernel(const float* __restrict__ KT,
                                                     const float* __restrict__ Pm,
                                                     const float* __restrict__ Q,
                                                     const float* __restrict__ rinv,
                                                     const float* __restrict__ cinv,
                                                     float* __restrict__ C1,
                                                     float* __restrict__ C2) {
    __shared__ unsigned smem_u[11392];   // max(ctx1: 2304+8576, ctx2: 9216+2176)
    __shared__ float inv[256];
    const int bh = blockIdx.y, b = bh / H, h = bh % H;
    const int tid = threadIdx.x, lane = tid & 31, w = tid >> 5;
    const int g = lane >> 2, tq = lane & 3;

    if (blockIdx.z == 0) {
        // ======== ctx1: m=d(64), n=s(256), k=t; C1 = (KT @ P) * inv[s] ========
        unsigned* As = smem_u;            // 64*36
        unsigned* Bs = smem_u + 2304;     // 32*268
        const int s0 = blockIdx.x * 256;
        const float* Ag = KT + (size_t)bh * DK * S;
        const float* Bg = Pm + (size_t)bh * S * S + s0;
        const int nw = w * 32;
        inv[tid] = rinv[bh * S + s0 + tid];
        __syncthreads();
        float c[16][4] = {};
        for (int k0 = 0; k0 < S; k0 += 32) {
            {
                int kq = tid & 7, kc = kq * 4, bkp = (kq >> 1) * 8 + (kq & 1);
                #pragma unroll
                for (int it = 0; it < 2; it++) {
                    int m = (tid >> 3) + it * 32;
                    float4 v = *(const float4*)(Ag + (size_t)m * S + k0 + kc);
                    unsigned* dst = &As[m * 36 + bkp];
                    dst[0] = tf32c(v.x); dst[2] = tf32c(v.y); dst[4] = tf32c(v.z); dst[6] = tf32c(v.w);
                }
            }
            {
                #pragma unroll
                for (int it = 0; it < 8; it++) {
                    int kr = (tid >> 6) + it * 4;
                    int nc = (tid & 63) * 4;
                    float4 v = *(const float4*)(Bg + (size_t)(k0 + kr) * S + nc);
                    uint4 u;
                    u.x = tf32c(v.x); u.y = tf32c(v.y); u.z = tf32c(v.z); u.w = tf32c(v.w);
                    *(uint4*)&Bs[kperm(kr) * 268 + nc] = u;
                }
            }
            __syncthreads();
            #pragma unroll
            for (int ks = 0; ks < 4; ks++) {
                unsigned a[4][4], bf[4][2];
                #pragma unroll
                for (int i = 0; i < 4; i++) {
                    int r = 16 * i + g;
                    uint2 x = *(const uint2*)&As[r * 36 + ks * 8 + 2 * tq];
                    uint2 y = *(const uint2*)&As[(r + 8) * 36 + ks * 8 + 2 * tq];
                    a[i][0] = x.x; a[i][1] = y.x; a[i][2] = x.y; a[i][3] = y.y;
                }
                #pragma unroll
                for (int j = 0; j < 4; j++) {
                    int col = nw + 8 * j + g;
                    bf[j][0] = Bs[(ks * 8 + 2 * tq) * 268 + col];
                    bf[j][1] = Bs[(ks * 8 + 2 * tq + 1) * 268 + col];
                }
                #pragma unroll
                for (int i = 0; i < 4; i++)
                    #pragma unroll
                    for (int j = 0; j < 4; j++) mma8(c[i * 4 + j], a[i], bf[j]);
            }
            __syncthreads();
        }
        #pragma unroll
        for (int i = 0; i < 4; i++) {
            int d = 16 * i + g;
            #pragma unroll
            for (int j = 0; j < 4; j++) {
                int sl = nw + 8 * j + 2 * tq;
                int s = s0 + sl;
                float* cc = c[i * 4 + j];
                float r0 = inv[sl], r1 = inv[sl + 1];
                size_t a0 = (size_t)(b * S + s) * D + h * DK + d;
                C1[a0]         = cc[0] * r0;
                C1[a0 + D]     = cc[1] * r1;
                C1[a0 + 8]     = cc[2] * r0;
                C1[a0 + D + 8] = cc[3] * r1;
            }
        }
    } else {
        // ======== ctx2: m=t(256), n=d(64), k=s; C2 = (P @ Q) * inv[t] ========
        unsigned* As = smem_u;            // 256*36
        unsigned* Bs = smem_u + 9216;     // 32*68
        const int t0 = blockIdx.x * 256;
        const float* Ag = Pm + ((size_t)bh * S + t0) * S;
        const float* Bg = Q + (size_t)b * S * D + h * DK;
        const int mw = (w >> 1) * 64, nw = (w & 1) * 32;
        inv[tid] = cinv[bh * S + t0 + tid];
        __syncthreads();
        float c[16][4] = {};
        for (int k0 = 0; k0 < S; k0 += 32) {
            {
                int kq = tid & 7, kc = kq * 4, bkp = (kq >> 1) * 8 + (kq & 1);
                #pragma unroll
                for (int it = 0; it < 8; it++) {
                    int m = (tid >> 3) + it * 32;
                    float4 v = *(const float4*)(Ag + (size_t)m * S + k0 + kc);
                    unsigned* dst = &As[m * 36 + bkp];
                    dst[0] = tf32c(v.x);
                    dst[2] = tf32c(v.y);
                    dst[4] = tf32c(v.z);
                    dst[6] = tf32c(v.w);
                }
            }
            {
                #pragma unroll
                for (int it = 0; it < 2; it++) {
                    int kr = (tid >> 4) + it * 16;
                    int nc = (tid & 15) * 4;
                    float4 v = *(const float4*)(Bg + (size_t)(k0 + kr) * D + nc);
                    uint4 u; u.x = tf32c(v.x); u.y = tf32c(v.y); u.z = tf32c(v.z); u.w = tf32c(v.w);
                    *(uint4*)&Bs[kperm(kr) * 68 + nc] = u;
                }
            }
            __syncthreads();
            #pragma unroll
            for (int ks = 0; ks < 4; ks++) {
                unsigned a[4][4], bf[2][2];
                #pragma unroll
                for (int i = 0; i < 4; i++) {
                    int r = mw + 16 * i + g;
                    uint2 x = *(const uint2*)&As[r * 36 + ks * 8 + 2 * tq];
                    uint2 y = *(const uint2*)&As[(r + 8) * 36 + ks * 8 + 2 * tq];
                    a[i][0] = x.x; a[i][1] = y.x; a[i][2] = x.y; a[i][3] = y.y;
                }
                #pragma unroll
                for (int j = 0; j < 4; j++) {
                    int col = nw + 8 * j + g;
                    bf[j & 1][0] = Bs[(ks * 8 + 2 * tq) * 68 + col];
                    bf[j & 1][1] = Bs[(ks * 8 + 2 * tq + 1) * 68 + col];
                    #pragma unroll
                    for (int i = 0; i < 4; i++) mma8(c[i * 4 + j], a[i], bf[j & 1]);
                }
            }
            __syncthreads();
        }
        #pragma unroll
        for (int i = 0; i < 4; i++) {
            int tl = mw + 16 * i + g;
            int t = t0 + tl;
            float ci0 = inv[tl], ci8 = inv[tl + 8];
            #pragma unroll
            for (int j = 0; j < 4; j++) {
                int dcol = nw + 8 * j + 2 * tq;
                float* cc = c[i * 4 + j];
                size_t a0 = (size_t)(b * S + t) * D + h * DK + dcol;
                *(float2*)(C2 + a0)                 = make_float2(cc[0] * ci0, cc[1] * ci0);
                *(float2*)(C2 + a0 + (size_t)8 * D) = make_float2(cc[2] * ci8, cc[3] * ci8);
            }
        }
    }
}

// ---------------- batched LayerNorm over last dim (768) ----------------
__global__ void ln_kernel(const float* __restrict__ x,
                          const float* __restrict__ g1, const float* __restrict__ b1,
                          const float* __restrict__ g2, const float* __restrict__ b2,
                          float* __restrict__ out) {
    int row = blockIdx.x, tid = threadIdx.x;
    const float* gg = (row < Bz * S) ? g1 : g2;
    const float* bb = (row < Bz * S) ? b1 : b2;
    const float* xr = x + (size_t)row * D;
    float v0 = xr[tid], v1 = xr[tid + 256], v2 = xr[tid + 512];
    float s = v0 + v1 + v2;
    __shared__ float red[8];
    #pragma unroll
    for (int o = 16; o; o >>= 1) s += __shfl_xor_sync(0xffffffffu, s, o);
    if ((tid & 31) == 0) red[tid >> 5] = s;
    __syncthreads();
    float tot = 0.f;
    #pragma unroll
    for (int i = 0; i < 8; i++) tot += red[i];
    float mu = tot * (1.0f / 768.0f);
    float d0 = v0 - mu, d1 = v1 - mu, d2 = v2 - mu;
    float q = d0 * d0 + d1 * d1 + d2 * d2;
    #pragma unroll
    for (int o = 16; o; o >>= 1) q += __shfl_xor_sync(0xffffffffu, q, o);
    __syncthreads();
    if ((tid & 31) == 0) red[tid >> 5] = q;
    __syncthreads();
    float var = 0.f;
    #pragma unroll
    for (int i = 0; i < 8; i++) var += red[i];
    var *= (1.0f / 768.0f);
    float rs = rsqrtf(var + 1e-5f);
    float* orow = out + (size_t)row * D;
    orow[tid]       = d0 * rs * gg[tid]       + bb[tid];
    orow[tid + 256] = d1 * rs * gg[tid + 256] + bb[tid + 256];
    orow[tid + 512] = d2 * rs * gg[tid + 512] + bb[tid + 512];
}

// ---------------- launch ----------------
extern "C" void kernel_launch(void* const* d_in, const int* in_sizes, int n_in,
                              void* d_out, int out_size) {
    const float* pro1 = (const float*)d_in[0];
    const float* pro2 = (const float*)d_in[1];
    const void*  mask = d_in[2];
    const float* W_Q  = (const float*)d_in[3];
    const float* W_K  = (const float*)d_in[4];
    const float* fc1  = (const float*)d_in[5];
    const float* g1   = (const float*)d_in[6];
    const float* b1   = (const float*)d_in[7];
    const float* g2   = (const float*)d_in[8];
    const float* b2   = (const float*)d_in[9];
    float* out = (float*)d_out;

    float *Qp, *Kp, *QTp, *KTp, *Pp, *CX, *Tp, *CP, *RI, *CI;
    cudaGetSymbolAddress((void**)&Qp, g_Q);
    cudaGetSymbolAddress((void**)&Kp, g_K);
    cudaGetSymbolAddress((void**)&QTp, g_QT);
    cudaGetSymbolAddress((void**)&KTp, g_KT);
    cudaGetSymbolAddress((void**)&Pp, g_P);
    cudaGetSymbolAddress((void**)&CX, g_ctx);
    cudaGetSymbolAddress((void**)&Tp, g_t);
    cudaGetSymbolAddress((void**)&CP, g_cpart);
    cudaGetSymbolAddress((void**)&RI, g_rinv);
    cudaGetSymbolAddress((void**)&CI, g_cinv);

    detect_mask_kernel<<<1, 256>>>((const unsigned int*)mask);

    // merged Q/K projections
    mm128_dual_kernel<<<dim3(6, 32, 2), 256>>>(pro1, W_Q, Qp, pro2, W_K, Kp);

    // merged transposes
    tr_kernel<<<dim3(32, 2, 2 * BH), dim3(32, 8)>>>(Qp, QTp, Kp, KTp);

    // scores -> P = exp(masked score)
    scoresT_kernel<<<dim3(8, 8, BH), 256>>>(Kp, QTp, mask, Pp);

    sums_kernel<<<dim3(8, BH), 256>>>(Pp, CP, CI);
    rinv_kernel<<<dim3(4, BH), 256>>>(CP, RI);

    // merged ctx1 + ctx2 (normalization in epilogue)
    ctx_kernel<<<dim3(4, BH, 2), 256>>>(KTp, Pp, Qp, RI, CI, CX, CX + (size_t)Bz * S * D);

    // merged output projection (both halves)
    mm128_kernel<<<dim3(6, 64), 256>>>(CX, fc1, Tp);

    ln_kernel<<<2 * Bz * S, 256>>>(Tp, g1, b1, g2, b2, out);
}

// round 14
// speedup vs baseline: 1.1780x; 1.1780x over previous
#include <cuda_runtime.h>
#include <cuda_fp16.h>
#include <cstdint>

#define Bz 4
#define S 1024
#define D 768
#define H 12
#define DK 64
#define BH (Bz*H)
#define NEGV -1e9f

// ---------------- scratch (device globals) ----------------
__device__ float  g_Q[Bz*S*D];
__device__ float  g_K[Bz*S*D];
__device__ float  g_QT[BH*DK*S];
__device__ float  g_KT[BH*DK*S];
__device__ __half g_sc[(size_t)BH*S*S];     // scores TRANSPOSED [bh][t][s], fp16 (masked = -inf)
__device__ float  g_ctx[2*Bz*S*D];          // ctx1 | ctx2
__device__ float  g_t[2*Bz*S*D];
__device__ float  g_cpart[(size_t)BH*64*S]; // per-(block,warp) partial col sums
__device__ float  g_rinv[BH*S];             // 1/sum_t exp  (per s)  -> ctx1
__device__ float  g_cinv[BH*S];             // 1/sum_s exp  (per t)  -> ctx2
__device__ int    g_mask_mode;              // 0=i32, 1=u8, 2=f32

// ---------------- helpers ----------------
__device__ __forceinline__ unsigned tf32c(float x) {
    unsigned u; asm("cvt.rna.tf32.f32 %0, %1;" : "=r"(u) : "f"(x)); return u;
}
__device__ __forceinline__ void mma8(float c[4], const unsigned a[4], const unsigned b[2]) {
    asm volatile(
        "mma.sync.aligned.m16n8k8.row.col.f32.tf32.tf32.f32 "
        "{%0,%1,%2,%3},{%4,%5,%6,%7},{%8,%9},{%0,%1,%2,%3};\n"
        : "+f"(c[0]), "+f"(c[1]), "+f"(c[2]), "+f"(c[3])
        : "r"(a[0]), "r"(a[1]), "r"(a[2]), "r"(a[3]), "r"(b[0]), "r"(b[1]));
}
__device__ __forceinline__ int kperm(int k) {  // within-chunk k (0..31) -> permuted slot
    return (k & ~7) + 2 * (k & 3) + ((k & 7) >> 2);
}

// ---------------- mask dtype sniffer ----------------
__global__ void detect_mask_kernel(const unsigned int* __restrict__ w) {
    __shared__ int s01, sf;
    if (threadIdx.x == 0) { s01 = 1; sf = 1; }
    __syncthreads();
    int a01 = 1, af = 1;
    for (int i = threadIdx.x; i < 4096; i += 256) {
        unsigned v = w[i];
        if (v != 0u && v != 1u) a01 = 0;
        if (v != 0u && v != 0x3F800000u) af = 0;
    }
    if (!a01) atomicAnd(&s01, 0);
    if (!af)  atomicAnd(&sf, 0);
    __syncthreads();
    if (threadIdx.x == 0) g_mask_mode = s01 ? 0 : (sf ? 2 : 1);
}

// ---------------- tf32 GEMM 128x128x32 body (R2/R9 exact) ----------------
__device__ __forceinline__ void mm128_body(const float* __restrict__ A,
                                           const float* __restrict__ B,
                                           float* __restrict__ C,
                                           int m0, int n0,
                                           unsigned* As, unsigned* Bs) {
    const int tid = threadIdx.x, lane = tid & 31, w = tid >> 5;
    const int g = lane >> 2, tq = lane & 3;
    const int mw = (w & 1) * 64, nw = (w >> 1) * 32;
    float c[16][4] = {};
    for (int k0 = 0; k0 < 768; k0 += 32) {
        {   // A: 128x32
            int kq = tid & 7, kc = kq * 4, bkp = (kq >> 1) * 8 + (kq & 1);
            #pragma unroll
            for (int it = 0; it < 4; it++) {
                int m = (tid >> 3) + it * 32;
                float4 v = *(const float4*)(A + (size_t)(m0 + m) * 768 + k0 + kc);
                unsigned* dst = &As[m * 36 + bkp];
                dst[0] = tf32c(v.x); dst[2] = tf32c(v.y); dst[4] = tf32c(v.z); dst[6] = tf32c(v.w);
            }
        }
        {   // B: 32x128 (row-major k x n)
            #pragma unroll
            for (int it = 0; it < 4; it++) {
                int kr = (tid >> 5) + it * 8;
                int nc = lane * 4;
                float4 v = *(const float4*)(B + (size_t)(k0 + kr) * 768 + n0 + nc);
                uint4 u; u.x = tf32c(v.x); u.y = tf32c(v.y); u.z = tf32c(v.z); u.w = tf32c(v.w);
                *(uint4*)&Bs[kperm(kr) * 132 + nc] = u;
            }
        }
        __syncthreads();
        #pragma unroll
        for (int ks = 0; ks < 4; ks++) {
            unsigned a[4][4], bf[4][2];
            #pragma unroll
            for (int i = 0; i < 4; i++) {
                int r = mw + 16 * i + g;
                uint2 x = *(const uint2*)&As[r * 36 + ks * 8 + 2 * tq];
                uint2 y = *(const uint2*)&As[(r + 8) * 36 + ks * 8 + 2 * tq];
                a[i][0] = x.x; a[i][1] = y.x; a[i][2] = x.y; a[i][3] = y.y;
            }
            #pragma unroll
            for (int j = 0; j < 4; j++) {
                int col = nw + 8 * j + g;
                bf[j][0] = Bs[(ks * 8 + 2 * tq) * 132 + col];
                bf[j][1] = Bs[(ks * 8 + 2 * tq + 1) * 132 + col];
            }
            #pragma unroll
            for (int i = 0; i < 4; i++)
                #pragma unroll
                for (int j = 0; j < 4; j++) mma8(c[i * 4 + j], a[i], bf[j]);
        }
        __syncthreads();
    }
    #pragma unroll
    for (int i = 0; i < 4; i++) {
        int r = m0 + mw + 16 * i + g;
        #pragma unroll
        for (int j = 0; j < 4; j++) {
            int col = n0 + nw + 8 * j + 2 * tq;
            *(float2*)(C + (size_t)r * 768 + col)       = make_float2(c[i*4+j][0], c[i*4+j][1]);
            *(float2*)(C + (size_t)(r + 8) * 768 + col) = make_float2(c[i*4+j][2], c[i*4+j][3]);
        }
    }
}

// merged Q/K projection: z=0 -> A1@B1->C1, z=1 -> A2@B2->C2
__global__ void __launch_bounds__(256, 2) mm128_dual_kernel(const float* __restrict__ A1,
                                                            const float* __restrict__ B1,
                                                            float* __restrict__ C1,
                                                            const float* __restrict__ A2,
                                                            const float* __restrict__ B2,
                                                            float* __restrict__ C2) {
    __shared__ unsigned As[128 * 36];
    __shared__ unsigned Bs[32 * 132];
    const int m0 = blockIdx.y * 128, n0 = blockIdx.x * 128;
    if (blockIdx.z == 0) mm128_body(A1, B1, C1, m0, n0, As, Bs);
    else                 mm128_body(A2, B2, C2, m0, n0, As, Bs);
}

// single GEMM (output projection)
__global__ void __launch_bounds__(256, 2) mm128_kernel(const float* __restrict__ A,
                                                       const float* __restrict__ B,
                                                       float* __restrict__ C) {
    __shared__ unsigned As[128 * 36];
    __shared__ unsigned Bs[32 * 132];
    mm128_body(A, B, C, blockIdx.y * 128, blockIdx.x * 128, As, Bs);
}

// ---------------- head transpose, merged Q/K: z in [0, 2*BH) ----------------
__global__ void tr_kernel(const float* __restrict__ Qm, float* __restrict__ QT,
                          const float* __restrict__ Km, float* __restrict__ KT) {
    __shared__ float tile[32][33];
    int z = blockIdx.z;
    const float* X = (z < BH) ? Qm : Km;
    float* XT = (z < BH) ? QT : KT;
    int bh = (z < BH) ? z : z - BH;
    int b = bh / H, h = bh % H;
    int s0 = blockIdx.x * 32, d0 = blockIdx.y * 32;
    int tx = threadIdx.x, ty = threadIdx.y;
    #pragma unroll
    for (int i = 0; i < 4; i++)
        tile[ty + 8 * i][tx] = X[(size_t)(b * S + s0 + ty + 8 * i) * D + h * DK + d0 + tx];
    __syncthreads();
    #pragma unroll
    for (int i = 0; i < 4; i++)
        XT[(size_t)(bh * DK + d0 + ty + 8 * i) * S + s0 + tx] = tile[tx][ty + 8 * i];
}

// ---------------- scoresT[bh][t][s] = (K_t . Q_s)/8, masked -> fp16 ----------------
__global__ void __launch_bounds__(256, 2) scoresT_kernel(const float* __restrict__ Kmat,
                                                         const float* __restrict__ QT,
                                                         const void* __restrict__ mask,
                                                         __half* __restrict__ scT) {
    __shared__ unsigned As[128 * 36];
    __shared__ unsigned Bs[32 * 132];
    const int bh = blockIdx.z, b = bh / H, h = bh % H;
    const int s0 = blockIdx.x * 128, t0 = blockIdx.y * 128;
    const float* Ag = Kmat + (size_t)(b * S + t0) * D + h * DK;
    const float* Bg = QT + (size_t)bh * DK * S + s0;
    const int tid = threadIdx.x, lane = tid & 31, w = tid >> 5;
    const int g = lane >> 2, tq = lane & 3;
    const int mw = (w & 1) * 64, nw = (w >> 1) * 32;
    float c[16][4] = {};
    #pragma unroll
    for (int k0 = 0; k0 < 64; k0 += 32) {
        {
            int kq = tid & 7, kc = kq * 4, bkp = (kq >> 1) * 8 + (kq & 1);
            #pragma unroll
            for (int it = 0; it < 4; it++) {
                int m = (tid >> 3) + it * 32;
                float4 v = *(const float4*)(Ag + (size_t)m * D + k0 + kc);
                unsigned* dst = &As[m * 36 + bkp];
                dst[0] = tf32c(v.x); dst[2] = tf32c(v.y); dst[4] = tf32c(v.z); dst[6] = tf32c(v.w);
            }
        }
        {
            #pragma unroll
            for (int it = 0; it < 4; it++) {
                int kr = (tid >> 5) + it * 8;
                int nc = lane * 4;
                float4 v = *(const float4*)(Bg + (size_t)(k0 + kr) * S + nc);
                uint4 u; u.x = tf32c(v.x); u.y = tf32c(v.y); u.z = tf32c(v.z); u.w = tf32c(v.w);
                *(uint4*)&Bs[kperm(kr) * 132 + nc] = u;
            }
        }
        __syncthreads();
        #pragma unroll
        for (int ks = 0; ks < 4; ks++) {
            unsigned a[4][4], bf[4][2];
            #pragma unroll
            for (int i = 0; i < 4; i++) {
                int r = mw + 16 * i + g;
                uint2 x = *(const uint2*)&As[r * 36 + ks * 8 + 2 * tq];
                uint2 y = *(const uint2*)&As[(r + 8) * 36 + ks * 8 + 2 * tq];
                a[i][0] = x.x; a[i][1] = y.x; a[i][2] = x.y; a[i][3] = y.y;
            }
            #pragma unroll
            for (int j = 0; j < 4; j++) {
                int col = nw + 8 * j + g;
                bf[j][0] = Bs[(ks * 8 + 2 * tq) * 132 + col];
                bf[j][1] = Bs[(ks * 8 + 2 * tq + 1) * 132 + col];
            }
            #pragma unroll
            for (int i = 0; i < 4; i++)
                #pragma unroll
                for (int j = 0; j < 4; j++) mma8(c[i * 4 + j], a[i], bf[j]);
        }
        __syncthreads();
    }
    const int mode = g_mask_mode;
    const int* m32 = (const int*)mask;
    const unsigned char* m8 = (const unsigned char*)mask;
    const float* mf = (const float*)mask;
    #pragma unroll
    for (int i = 0; i < 4; i++) {
        int rA = t0 + mw + 16 * i + g;
        #pragma unroll
        for (int j = 0; j < 4; j++) {
            int cs = s0 + nw + 8 * j + 2 * tq;
            float* cc = c[i * 4 + j];
            size_t iA = ((size_t)bh * S + rA) * S + cs;
            size_t iB = iA + (size_t)8 * S;
            float2 o0 = make_float2(cc[0] * 0.125f, cc[1] * 0.125f);
            float2 o1 = make_float2(cc[2] * 0.125f, cc[3] * 0.125f);
            if (mode == 0) {
                int2 qa = *(const int2*)(m32 + iA); int2 qb = *(const int2*)(m32 + iB);
                if (qa.x) o0.x = NEGV; if (qa.y) o0.y = NEGV;
                if (qb.x) o1.x = NEGV; if (qb.y) o1.y = NEGV;
            } else if (mode == 1) {
                uchar2 qa = *(const uchar2*)(m8 + iA); uchar2 qb = *(const uchar2*)(m8 + iB);
                if (qa.x) o0.x = NEGV; if (qa.y) o0.y = NEGV;
                if (qb.x) o1.x = NEGV; if (qb.y) o1.y = NEGV;
            } else {
                float2 qa = *(const float2*)(mf + iA); float2 qb = *(const float2*)(mf + iB);
                if (qa.x != 0.0f) o0.x = NEGV; if (qa.y != 0.0f) o0.y = NEGV;
                if (qb.x != 0.0f) o1.x = NEGV; if (qb.y != 0.0f) o1.y = NEGV;
            }
            // -1e9 rounds to fp16 -inf; expf(-inf) = 0 downstream (intended)
            *(__half2*)(scT + iA) = __floats2half2_rn(o0.x, o0.y);
            *(__half2*)(scT + iB) = __floats2half2_rn(o1.x, o1.y);
        }
    }
}

// ---------------- fused dual exp-sums over fp16 scores (one pass, deterministic) ----------------
__global__ void __launch_bounds__(256) sums_kernel(const __half* __restrict__ scT,
                                                   float* __restrict__ cpart,
                                                   float* __restrict__ cinv) {
    int bh = blockIdx.y, blk = blockIdx.x;
    int w = threadIdx.x >> 5, lane = threadIdx.x & 31;
    int t0 = blk * 128 + w * 16;
    float colacc[8][4] = {};
    const __half* base = scT + ((size_t)bh * S + t0) * S;
    for (int r = 0; r < 16; r++) {
        const __half* row = base + (size_t)r * S;
        float rsum = 0.f;
        #pragma unroll
        for (int k = 0; k < 8; k++) {
            uint2 u = *(const uint2*)(row + k * 128 + lane * 4);
            float2 fa = __half22float2(*(const __half2*)&u.x);
            float2 fb = __half22float2(*(const __half2*)&u.y);
            float e0 = __expf(fa.x), e1 = __expf(fa.y), e2 = __expf(fb.x), e3 = __expf(fb.y);
            colacc[k][0] += e0; colacc[k][1] += e1;
            colacc[k][2] += e2; colacc[k][3] += e3;
            rsum += (e0 + e1) + (e2 + e3);
        }
        #pragma unroll
        for (int o = 16; o; o >>= 1) rsum += __shfl_xor_sync(0xffffffffu, rsum, o);
        if (lane == 0) cinv[bh * S + t0 + r] = 1.0f / rsum;
    }
    float* cp = cpart + ((size_t)bh * 64 + blk * 8 + w) * S;
    #pragma unroll
    for (int k = 0; k < 8; k++)
        *(float4*)(cp + k * 128 + lane * 4) =
            make_float4(colacc[k][0], colacc[k][1], colacc[k][2], colacc[k][3]);
}

__global__ void rinv_kernel(const float* __restrict__ cpart, float* __restrict__ rinv) {
    int bh = blockIdx.y;
    int s = blockIdx.x * 256 + threadIdx.x;
    const float* p = cpart + (size_t)bh * 64 * S + s;
    float sum = 0.f;
    #pragma unroll
    for (int j = 0; j < 64; j++) sum += p[(size_t)j * S];
    rinv[bh * S + s] = 1.0f / sum;
}

// ---------------- merged ctx: z=0 -> ctx1 body, z=1 -> ctx2 body (fp16 scores in) ----------------
__global__ void __launch_bounds__(256, 2) ctx_kernel(const float* __restrict__ KT,
                                                     const __half* __restrict__ scT,
                                                     const float* __restrict__ Q,
                                                     const float* __restrict__ rinv,
                                                     const float* __restrict__ cinv,
                                                     float* __restrict__ C1,
                                                     float* __restrict__ C2) {
    __shared__ unsigned smem_u[11392];   // max(ctx1: 2304+8576, ctx2: 9216+2176)
    __shared__ float inv[256];
    const int bh = blockIdx.y, b = bh / H, h = bh % H;
    const int tid = threadIdx.x, lane = tid & 31, w = tid >> 5;
    const int g = lane >> 2, tq = lane & 3;

    if (blockIdx.z == 0) {
        // ======== ctx1: m=d(64), n=s(256), k=t ========
        unsigned* As = smem_u;            // 64*36
        unsigned* Bs = smem_u + 2304;     // 32*268
        const int s0 = blockIdx.x * 256;
        const float* Ag = KT + (size_t)bh * DK * S;
        const __half* Bg = scT + (size_t)bh * S * S + s0;
        const int nw = w * 32;
        inv[tid] = rinv[bh * S + s0 + tid];
        __syncthreads();
        float c[16][4] = {};
        for (int k0 = 0; k0 < S; k0 += 32) {
            {
                int kq = tid & 7, kc = kq * 4, bkp = (kq >> 1) * 8 + (kq & 1);
                #pragma unroll
                for (int it = 0; it < 2; it++) {
                    int m = (tid >> 3) + it * 32;
                    float4 v = *(const float4*)(Ag + (size_t)m * S + k0 + kc);
                    unsigned* dst = &As[m * 36 + bkp];
                    dst[0] = tf32c(v.x); dst[2] = tf32c(v.y); dst[4] = tf32c(v.z); dst[6] = tf32c(v.w);
                }
            }
            {
                #pragma unroll
                for (int it = 0; it < 8; it++) {
                    int kr = (tid >> 6) + it * 4;
                    int nc = (tid & 63) * 4;
                    uint2 uv = *(const uint2*)(Bg + (size_t)(k0 + kr) * S + nc);
                    float2 fa = __half22float2(*(const __half2*)&uv.x);
                    float2 fb = __half22float2(*(const __half2*)&uv.y);
                    uint4 u;
                    u.x = tf32c(__expf(fa.x) * inv[nc + 0]);
                    u.y = tf32c(__expf(fa.y) * inv[nc + 1]);
                    u.z = tf32c(__expf(fb.x) * inv[nc + 2]);
                    u.w = tf32c(__expf(fb.y) * inv[nc + 3]);
                    *(uint4*)&Bs[kperm(kr) * 268 + nc] = u;
                }
            }
            __syncthreads();
            #pragma unroll
            for (int ks = 0; ks < 4; ks++) {
                unsigned a[4][4], bf[4][2];
                #pragma unroll
                for (int i = 0; i < 4; i++) {
                    int r = 16 * i + g;
                    uint2 x = *(const uint2*)&As[r * 36 + ks * 8 + 2 * tq];
                    uint2 y = *(const uint2*)&As[(r + 8) * 36 + ks * 8 + 2 * tq];
                    a[i][0] = x.x; a[i][1] = y.x; a[i][2] = x.y; a[i][3] = y.y;
                }
                #pragma unroll
                for (int j = 0; j < 4; j++) {
                    int col = nw + 8 * j + g;
                    bf[j][0] = Bs[(ks * 8 + 2 * tq) * 268 + col];
                    bf[j][1] = Bs[(ks * 8 + 2 * tq + 1) * 268 + col];
                }
                #pragma unroll
                for (int i = 0; i < 4; i++)
                    #pragma unroll
                    for (int j = 0; j < 4; j++) mma8(c[i * 4 + j], a[i], bf[j]);
            }
            __syncthreads();
        }
        #pragma unroll
        for (int i = 0; i < 4; i++) {
            int d = 16 * i + g;
            #pragma unroll
            for (int j = 0; j < 4; j++) {
                int s = s0 + nw + 8 * j + 2 * tq;
                float* cc = c[i * 4 + j];
                size_t a0 = (size_t)(b * S + s) * D + h * DK + d;
                C1[a0]         = cc[0];
                C1[a0 + D]     = cc[1];
                C1[a0 + 8]     = cc[2];
                C1[a0 + D + 8] = cc[3];
            }
        }
    } else {
        // ======== ctx2: m=t(256), n=d(64), k=s ========
        unsigned* As = smem_u;            // 256*36
        unsigned* Bs = smem_u + 9216;     // 32*68
        const int t0 = blockIdx.x * 256;
        const __half* Ag = scT + ((size_t)bh * S + t0) * S;
        const float* Bg = Q + (size_t)b * S * D + h * DK;
        const int mw = (w >> 1) * 64, nw = (w & 1) * 32;
        inv[tid] = cinv[bh * S + t0 + tid];
        __syncthreads();
        float c[16][4] = {};
        for (int k0 = 0; k0 < S; k0 += 32) {
            {
                int kq = tid & 7, kc = kq * 4, bkp = (kq >> 1) * 8 + (kq & 1);
                #pragma unroll
                for (int it = 0; it < 8; it++) {
                    int m = (tid >> 3) + it * 32;
                    uint2 uv = *(const uint2*)(Ag + (size_t)m * S + k0 + kc);
                    float2 fa = __half22float2(*(const __half2*)&uv.x);
                    float2 fb = __half22float2(*(const __half2*)&uv.y);
                    float ci = inv[m];
                    unsigned* dst = &As[m * 36 + bkp];
                    dst[0] = tf32c(__expf(fa.x) * ci);
                    dst[2] = tf32c(__expf(fa.y) * ci);
                    dst[4] = tf32c(__expf(fb.x) * ci);
                    dst[6] = tf32c(__expf(fb.y) * ci);
                }
            }
            {
                #pragma unroll
                for (int it = 0; it < 2; it++) {
                    int kr = (tid >> 4) + it * 16;
                    int nc = (tid & 15) * 4;
                    float4 v = *(const float4*)(Bg + (size_t)(k0 + kr) * D + nc);
                    uint4 u; u.x = tf32c(v.x); u.y = tf32c(v.y); u.z = tf32c(v.z); u.w = tf32c(v.w);
                    *(uint4*)&Bs[kperm(kr) * 68 + nc] = u;
                }
            }
            __syncthreads();
            #pragma unroll
            for (int ks = 0; ks < 4; ks++) {
                unsigned a[4][4], bf[2][2];
                #pragma unroll
                for (int i = 0; i < 4; i++) {
                    int r = mw + 16 * i + g;
                    uint2 x = *(const uint2*)&As[r * 36 + ks * 8 + 2 * tq];
                    uint2 y = *(const uint2*)&As[(r + 8) * 36 + ks * 8 + 2 * tq];
                    a[i][0] = x.x; a[i][1] = y.x; a[i][2] = x.y; a[i][3] = y.y;
                }
                #pragma unroll
                for (int j = 0; j < 4; j++) {
                    int col = nw + 8 * j + g;
                    bf[j & 1][0] = Bs[(ks * 8 + 2 * tq) * 68 + col];
                    bf[j & 1][1] = Bs[(ks * 8 + 2 * tq + 1) * 68 + col];
                    #pragma unroll
                    for (int i = 0; i < 4; i++) mma8(c[i * 4 + j], a[i], bf[j & 1]);
                }
            }
            __syncthreads();
        }
        #pragma unroll
        for (int i = 0; i < 4; i++) {
            int t = t0 + mw + 16 * i + g;
            #pragma unroll
            for (int j = 0; j < 4; j++) {
                int dcol = nw + 8 * j + 2 * tq;
                float* cc = c[i * 4 + j];
                size_t a0 = (size_t)(b * S + t) * D + h * DK + dcol;
                *(float2*)(C2 + a0)                 = make_float2(cc[0], cc[1]);
                *(float2*)(C2 + a0 + (size_t)8 * D) = make_float2(cc[2], cc[3]);
            }
        }
    }
}

// ---------------- batched LayerNorm over last dim (768) ----------------
__global__ void ln_kernel(const float* __restrict__ x,
                          const float* __restrict__ g1, const float* __restrict__ b1,
                          const float* __restrict__ g2, const float* __restrict__ b2,
                          float* __restrict__ out) {
    int row = blockIdx.x, tid = threadIdx.x;
    const float* gg = (row < Bz * S) ? g1 : g2;
    const float* bb = (row < Bz * S) ? b1 : b2;
    const float* xr = x + (size_t)row * D;
    float v0 = xr[tid], v1 = xr[tid + 256], v2 = xr[tid + 512];
    float s = v0 + v1 + v2;
    __shared__ float red[8];
    #pragma unroll
    for (int o = 16; o; o >>= 1) s += __shfl_xor_sync(0xffffffffu, s, o);
    if ((tid & 31) == 0) red[tid >> 5] = s;
    __syncthreads();
    float tot = 0.f;
    #pragma unroll
    for (int i = 0; i < 8; i++) tot += red[i];
    float mu = tot * (1.0f / 768.0f);
    float d0 = v0 - mu, d1 = v1 - mu, d2 = v2 - mu;
    float q = d0 * d0 + d1 * d1 + d2 * d2;
    #pragma unroll
    for (int o = 16; o; o >>= 1) q += __shfl_xor_sync(0xffffffffu, q, o);
    __syncthreads();
    if ((tid & 31) == 0) red[tid >> 5] = q;
    __syncthreads();
    float var = 0.f;
    #pragma unroll
    for (int i = 0; i < 8; i++) var += red[i];
    var *= (1.0f / 768.0f);
    float rs = rsqrtf(var + 1e-5f);
    float* orow = out + (size_t)row * D;
    orow[tid]       = d0 * rs * gg[tid]       + bb[tid];
    orow[tid + 256] = d1 * rs * gg[tid + 256] + bb[tid + 256];
    orow[tid + 512] = d2 * rs * gg[tid + 512] + bb[tid + 512];
}

// ---------------- launch ----------------
extern "C" void kernel_launch(void* const* d_in, const int* in_sizes, int n_in,
                              void* d_out, int out_size) {
    const float* pro1 = (const float*)d_in[0];
    const float* pro2 = (const float*)d_in[1];
    const void*  mask = d_in[2];
    const float* W_Q  = (const float*)d_in[3];
    const float* W_K  = (const float*)d_in[4];
    const float* fc1  = (const float*)d_in[5];
    const float* g1   = (const float*)d_in[6];
    const float* b1   = (const float*)d_in[7];
    const float* g2   = (const float*)d_in[8];
    const float* b2   = (const float*)d_in[9];
    float* out = (float*)d_out;

    float *Qp, *Kp, *QTp, *KTp, *CX, *Tp, *CP, *RI, *CI;
    __half* Sp;
    cudaGetSymbolAddress((void**)&Qp, g_Q);
    cudaGetSymbolAddress((void**)&Kp, g_K);
    cudaGetSymbolAddress((void**)&QTp, g_QT);
    cudaGetSymbolAddress((void**)&KTp, g_KT);
    cudaGetSymbolAddress((void**)&Sp, g_sc);
    cudaGetSymbolAddress((void**)&CX, g_ctx);
    cudaGetSymbolAddress((void**)&Tp, g_t);
    cudaGetSymbolAddress((void**)&CP, g_cpart);
    cudaGetSymbolAddress((void**)&RI, g_rinv);
    cudaGetSymbolAddress((void**)&CI, g_cinv);

    detect_mask_kernel<<<1, 256>>>((const unsigned int*)mask);

    // merged Q/K projections
    mm128_dual_kernel<<<dim3(6, 32, 2), 256>>>(pro1, W_Q, Qp, pro2, W_K, Kp);

    // merged transposes
    tr_kernel<<<dim3(32, 2, 2 * BH), dim3(32, 8)>>>(Qp, QTp, Kp, KTp);

    scoresT_kernel<<<dim3(8, 8, BH), 256>>>(Kp, QTp, mask, Sp);

    sums_kernel<<<dim3(8, BH), 256>>>(Sp, CP, CI);
    rinv_kernel<<<dim3(4, BH), 256>>>(CP, RI);

    // merged ctx1 + ctx2
    ctx_kernel<<<dim3(4, BH, 2), 256>>>(KTp, Sp, Qp, RI, CI, CX, CX + (size_t)Bz * S * D);

    // merged output projection (both halves)
    mm128_kernel<<<dim3(6, 64), 256>>>(CX, fc1, Tp);

    ln_kernel<<<2 * Bz * S, 256>>>(Tp, g1, b1, g2, b2, out);
}

// round 15
// speedup vs baseline: 1.2174x; 1.0334x over previous
#include <cuda_runtime.h>
#include <cuda_fp16.h>
#include <cstdint>

#define Bz 4
#define S 1024
#define D 768
#define H 12
#define DK 64
#define BH (Bz*H)
#define NEGV -1e9f

// ---------------- scratch (device globals) ----------------
__device__ float  g_Q[Bz*S*D];
__device__ float  g_K[Bz*S*D];
__device__ float  g_QT[BH*DK*S];
__device__ float  g_KT[BH*DK*S];
__device__ __half g_sc[(size_t)BH*S*S];     // scores TRANSPOSED [bh][t][s], fp16 (masked = -inf)
__device__ float  g_ctx[2*Bz*S*D];          // ctx1 | ctx2
__device__ float  g_t[2*Bz*S*D];
__device__ float  g_cpart[(size_t)BH*64*S];
__device__ float  g_rinv[BH*S];
__device__ float  g_cinv[BH*S];
__device__ int    g_mask_mode;

// dynamic smem sizes (bytes)
#define MM_SMEM   ((128*68 + 64*132) * 4)   // 68608
#define SC_SMEM   ((128*68 + 64*132) * 4)   // 68608
#define CTX_SMEM  ((256*68 + 64*68) * 4)    // 87040 (>= ctx1's 64*68+64*268)

// ---------------- helpers ----------------
__device__ __forceinline__ unsigned tf32c(float x) {
    unsigned u; asm("cvt.rna.tf32.f32 %0, %1;" : "=r"(u) : "f"(x)); return u;
}
__device__ __forceinline__ void mma8(float c[4], const unsigned a[4], const unsigned b[2]) {
    asm volatile(
        "mma.sync.aligned.m16n8k8.row.col.f32.tf32.tf32.f32 "
        "{%0,%1,%2,%3},{%4,%5,%6,%7},{%8,%9},{%0,%1,%2,%3};\n"
        : "+f"(c[0]), "+f"(c[1]), "+f"(c[2]), "+f"(c[3])
        : "r"(a[0]), "r"(a[1]), "r"(a[2]), "r"(a[3]), "r"(b[0]), "r"(b[1]));
}
__device__ __forceinline__ int kperm(int k) {  // within-32 k -> permuted slot
    return (k & ~7) + 2 * (k & 3) + ((k & 7) >> 2);
}

// ---------------- mask dtype sniffer ----------------
__global__ void detect_mask_kernel(const unsigned int* __restrict__ w) {
    __shared__ int s01, sf;
    if (threadIdx.x == 0) { s01 = 1; sf = 1; }
    __syncthreads();
    int a01 = 1, af = 1;
    for (int i = threadIdx.x; i < 4096; i += 256) {
        unsigned v = w[i];
        if (v != 0u && v != 1u) a01 = 0;
        if (v != 0u && v != 0x3F800000u) af = 0;
    }
    if (!a01) atomicAnd(&s01, 0);
    if (!af)  atomicAnd(&sf, 0);
    __syncthreads();
    if (threadIdx.x == 0) g_mask_mode = s01 ? 0 : (sf ? 2 : 1);
}

// ---------------- tf32 GEMM 128x128, k-chunk 64, dynamic smem ----------------
// As: [128][68] (two 32-halves per row), Bs: [64][132]
__device__ __forceinline__ void mm128_body(const float* __restrict__ A,
                                           const float* __restrict__ B,
                                           float* __restrict__ C,
                                           int m0, int n0, unsigned* dyn) {
    unsigned* As = dyn;
    unsigned* Bs = dyn + 128 * 68;
    const int tid = threadIdx.x, lane = tid & 31, w = tid >> 5;
    const int g = lane >> 2, tq = lane & 3;
    const int mw = (w & 1) * 64, nw = (w >> 1) * 32;
    const int kq6 = tid & 15, ahalf = kq6 >> 3, kq = kq6 & 7;
    const int akc = ahalf * 32 + kq * 4;
    const int abkp = ahalf * 32 + (kq >> 1) * 8 + (kq & 1);
    float c[16][4] = {};
    for (int k0 = 0; k0 < 768; k0 += 64) {
        #pragma unroll
        for (int it = 0; it < 8; it++) {   // A: 128x64
            int m = (tid >> 4) + it * 16;
            float4 v = *(const float4*)(A + (size_t)(m0 + m) * 768 + k0 + akc);
            unsigned* dst = &As[m * 68 + abkp];
            dst[0] = tf32c(v.x); dst[2] = tf32c(v.y); dst[4] = tf32c(v.z); dst[6] = tf32c(v.w);
        }
        #pragma unroll
        for (int it = 0; it < 8; it++) {   // B: 64x128
            int kr6 = (tid >> 5) + it * 8;
            int row = (kr6 >> 5) * 32 + kperm(kr6 & 31);
            int nc = lane * 4;
            float4 v = *(const float4*)(B + (size_t)(k0 + kr6) * 768 + n0 + nc);
            uint4 u; u.x = tf32c(v.x); u.y = tf32c(v.y); u.z = tf32c(v.z); u.w = tf32c(v.w);
            *(uint4*)&Bs[row * 132 + nc] = u;
        }
        __syncthreads();
        #pragma unroll
        for (int ks = 0; ks < 8; ks++) {
            const int kb = ((ks >> 2) << 5) + ((ks & 3) << 3) + 2 * tq;
            unsigned a[4][4], bf[4][2];
            #pragma unroll
            for (int i = 0; i < 4; i++) {
                int r = mw + 16 * i + g;
                uint2 x = *(const uint2*)&As[r * 68 + kb];
                uint2 y = *(const uint2*)&As[(r + 8) * 68 + kb];
                a[i][0] = x.x; a[i][1] = y.x; a[i][2] = x.y; a[i][3] = y.y;
            }
            #pragma unroll
            for (int j = 0; j < 4; j++) {
                int col = nw + 8 * j + g;
                bf[j][0] = Bs[kb * 132 + col];
                bf[j][1] = Bs[(kb + 1) * 132 + col];
            }
            #pragma unroll
            for (int i = 0; i < 4; i++)
                #pragma unroll
                for (int j = 0; j < 4; j++) mma8(c[i * 4 + j], a[i], bf[j]);
        }
        __syncthreads();
    }
    #pragma unroll
    for (int i = 0; i < 4; i++) {
        int r = m0 + mw + 16 * i + g;
        #pragma unroll
        for (int j = 0; j < 4; j++) {
            int col = n0 + nw + 8 * j + 2 * tq;
            *(float2*)(C + (size_t)r * 768 + col)       = make_float2(c[i*4+j][0], c[i*4+j][1]);
            *(float2*)(C + (size_t)(r + 8) * 768 + col) = make_float2(c[i*4+j][2], c[i*4+j][3]);
        }
    }
}

__global__ void __launch_bounds__(256, 2) mm128_dual_kernel(const float* __restrict__ A1,
                                                            const float* __restrict__ B1,
                                                            float* __restrict__ C1,
                                                            const float* __restrict__ A2,
                                                            const float* __restrict__ B2,
                                                            float* __restrict__ C2) {
    extern __shared__ unsigned dyn_u[];
    const int m0 = blockIdx.y * 128, n0 = blockIdx.x * 128;
    if (blockIdx.z == 0) mm128_body(A1, B1, C1, m0, n0, dyn_u);
    else                 mm128_body(A2, B2, C2, m0, n0, dyn_u);
}

__global__ void __launch_bounds__(256, 2) mm128_kernel(const float* __restrict__ A,
                                                       const float* __restrict__ B,
                                                       float* __restrict__ C) {
    extern __shared__ unsigned dyn_u[];
    mm128_body(A, B, C, blockIdx.y * 128, blockIdx.x * 128, dyn_u);
}

// ---------------- head transpose, merged Q/K ----------------
__global__ void tr_kernel(const float* __restrict__ Qm, float* __restrict__ QT,
                          const float* __restrict__ Km, float* __restrict__ KT) {
    __shared__ float tile[32][33];
    int z = blockIdx.z;
    const float* X = (z < BH) ? Qm : Km;
    float* XT = (z < BH) ? QT : KT;
    int bh = (z < BH) ? z : z - BH;
    int b = bh / H, h = bh % H;
    int s0 = blockIdx.x * 32, d0 = blockIdx.y * 32;
    int tx = threadIdx.x, ty = threadIdx.y;
    #pragma unroll
    for (int i = 0; i < 4; i++)
        tile[ty + 8 * i][tx] = X[(size_t)(b * S + s0 + ty + 8 * i) * D + h * DK + d0 + tx];
    __syncthreads();
    #pragma unroll
    for (int i = 0; i < 4; i++)
        XT[(size_t)(bh * DK + d0 + ty + 8 * i) * S + s0 + tx] = tile[tx][ty + 8 * i];
}

// ---------------- scoresT: single load phase (K=64), fp16 out ----------------
__global__ void __launch_bounds__(256, 2) scoresT_kernel(const float* __restrict__ Kmat,
                                                         const float* __restrict__ QT,
                                                         const void* __restrict__ mask,
                                                         __half* __restrict__ scT) {
    extern __shared__ unsigned dyn_u[];
    unsigned* As = dyn_u;
    unsigned* Bs = dyn_u + 128 * 68;
    const int bh = blockIdx.z, b = bh / H, h = bh % H;
    const int s0 = blockIdx.x * 128, t0 = blockIdx.y * 128;
    const float* Ag = Kmat + (size_t)(b * S + t0) * D + h * DK;
    const float* Bg = QT + (size_t)bh * DK * S + s0;
    const int tid = threadIdx.x, lane = tid & 31, w = tid >> 5;
    const int g = lane >> 2, tq = lane & 3;
    const int mw = (w & 1) * 64, nw = (w >> 1) * 32;
    {
        const int kq6 = tid & 15, ahalf = kq6 >> 3, kq = kq6 & 7;
        const int akc = ahalf * 32 + kq * 4;
        const int abkp = ahalf * 32 + (kq >> 1) * 8 + (kq & 1);
        #pragma unroll
        for (int it = 0; it < 8; it++) {   // A = K tile 128x64
            int m = (tid >> 4) + it * 16;
            float4 v = *(const float4*)(Ag + (size_t)m * D + akc);
            unsigned* dst = &As[m * 68 + abkp];
            dst[0] = tf32c(v.x); dst[2] = tf32c(v.y); dst[4] = tf32c(v.z); dst[6] = tf32c(v.w);
        }
        #pragma unroll
        for (int it = 0; it < 8; it++) {   // B = QT tile 64x128
            int kr6 = (tid >> 5) + it * 8;
            int row = (kr6 >> 5) * 32 + kperm(kr6 & 31);
            int nc = lane * 4;
            float4 v = *(const float4*)(Bg + (size_t)kr6 * S + nc);
            uint4 u; u.x = tf32c(v.x); u.y = tf32c(v.y); u.z = tf32c(v.z); u.w = tf32c(v.w);
            *(uint4*)&Bs[row * 132 + nc] = u;
        }
    }
    __syncthreads();
    float c[16][4] = {};
    #pragma unroll
    for (int ks = 0; ks < 8; ks++) {
        const int kb = ((ks >> 2) << 5) + ((ks & 3) << 3) + 2 * tq;
        unsigned a[4][4], bf[4][2];
        #pragma unroll
        for (int i = 0; i < 4; i++) {
            int r = mw + 16 * i + g;
            uint2 x = *(const uint2*)&As[r * 68 + kb];
            uint2 y = *(const uint2*)&As[(r + 8) * 68 + kb];
            a[i][0] = x.x; a[i][1] = y.x; a[i][2] = x.y; a[i][3] = y.y;
        }
        #pragma unroll
        for (int j = 0; j < 4; j++) {
            int col = nw + 8 * j + g;
            bf[j][0] = Bs[kb * 132 + col];
            bf[j][1] = Bs[(kb + 1) * 132 + col];
        }
        #pragma unroll
        for (int i = 0; i < 4; i++)
            #pragma unroll
            for (int j = 0; j < 4; j++) mma8(c[i * 4 + j], a[i], bf[j]);
    }
    const int mode = g_mask_mode;
    const int* m32 = (const int*)mask;
    const unsigned char* m8 = (const unsigned char*)mask;
    const float* mf = (const float*)mask;
    #pragma unroll
    for (int i = 0; i < 4; i++) {
        int rA = t0 + mw + 16 * i + g;
        #pragma unroll
        for (int j = 0; j < 4; j++) {
            int cs = s0 + nw + 8 * j + 2 * tq;
            float* cc = c[i * 4 + j];
            size_t iA = ((size_t)bh * S + rA) * S + cs;
            size_t iB = iA + (size_t)8 * S;
            float2 o0 = make_float2(cc[0] * 0.125f, cc[1] * 0.125f);
            float2 o1 = make_float2(cc[2] * 0.125f, cc[3] * 0.125f);
            if (mode == 0) {
                int2 qa = *(const int2*)(m32 + iA); int2 qb = *(const int2*)(m32 + iB);
                if (qa.x) o0.x = NEGV; if (qa.y) o0.y = NEGV;
                if (qb.x) o1.x = NEGV; if (qb.y) o1.y = NEGV;
            } else if (mode == 1) {
                uchar2 qa = *(const uchar2*)(m8 + iA); uchar2 qb = *(const uchar2*)(m8 + iB);
                if (qa.x) o0.x = NEGV; if (qa.y) o0.y = NEGV;
                if (qb.x) o1.x = NEGV; if (qb.y) o1.y = NEGV;
            } else {
                float2 qa = *(const float2*)(mf + iA); float2 qb = *(const float2*)(mf + iB);
                if (qa.x != 0.0f) o0.x = NEGV; if (qa.y != 0.0f) o0.y = NEGV;
                if (qb.x != 0.0f) o1.x = NEGV; if (qb.y != 0.0f) o1.y = NEGV;
            }
            *(__half2*)(scT + iA) = __floats2half2_rn(o0.x, o0.y);
            *(__half2*)(scT + iB) = __floats2half2_rn(o1.x, o1.y);
        }
    }
}

// ---------------- fused dual exp-sums over fp16 scores (R14 exact) ----------------
__global__ void __launch_bounds__(256) sums_kernel(const __half* __restrict__ scT,
                                                   float* __restrict__ cpart,
                                                   float* __restrict__ cinv) {
    int bh = blockIdx.y, blk = blockIdx.x;
    int w = threadIdx.x >> 5, lane = threadIdx.x & 31;
    int t0 = blk * 128 + w * 16;
    float colacc[8][4] = {};
    const __half* base = scT + ((size_t)bh * S + t0) * S;
    for (int r = 0; r < 16; r++) {
        const __half* row = base + (size_t)r * S;
        float rsum = 0.f;
        #pragma unroll
        for (int k = 0; k < 8; k++) {
            uint2 u = *(const uint2*)(row + k * 128 + lane * 4);
            float2 fa = __half22float2(*(const __half2*)&u.x);
            float2 fb = __half22float2(*(const __half2*)&u.y);
            float e0 = __expf(fa.x), e1 = __expf(fa.y), e2 = __expf(fb.x), e3 = __expf(fb.y);
            colacc[k][0] += e0; colacc[k][1] += e1;
            colacc[k][2] += e2; colacc[k][3] += e3;
            rsum += (e0 + e1) + (e2 + e3);
        }
        #pragma unroll
        for (int o = 16; o; o >>= 1) rsum += __shfl_xor_sync(0xffffffffu, rsum, o);
        if (lane == 0) cinv[bh * S + t0 + r] = 1.0f / rsum;
    }
    float* cp = cpart + ((size_t)bh * 64 + blk * 8 + w) * S;
    #pragma unroll
    for (int k = 0; k < 8; k++)
        *(float4*)(cp + k * 128 + lane * 4) =
            make_float4(colacc[k][0], colacc[k][1], colacc[k][2], colacc[k][3]);
}

__global__ void rinv_kernel(const float* __restrict__ cpart, float* __restrict__ rinv) {
    int bh = blockIdx.y;
    int s = blockIdx.x * 256 + threadIdx.x;
    const float* p = cpart + (size_t)bh * 64 * S + s;
    float sum = 0.f;
    #pragma unroll
    for (int j = 0; j < 64; j++) sum += p[(size_t)j * S];
    rinv[bh * S + s] = 1.0f / sum;
}

// ---------------- merged ctx, k-chunk 64, dynamic smem ----------------
__global__ void __launch_bounds__(256, 2) ctx_kernel(const float* __restrict__ KT,
                                                     const __half* __restrict__ scT,
                                                     const float* __restrict__ Q,
                                                     const float* __restrict__ rinv,
                                                     const float* __restrict__ cinv,
                                                     float* __restrict__ C1,
                                                     float* __restrict__ C2) {
    extern __shared__ unsigned dyn_u[];
    __shared__ float inv[256];
    const int bh = blockIdx.y, b = bh / H, h = bh % H;
    const int tid = threadIdx.x, lane = tid & 31, w = tid >> 5;
    const int g = lane >> 2, tq = lane & 3;

    if (blockIdx.z == 0) {
        // ======== ctx1: m=d(64), n=s(256), k=t. As [64][68], Bs [64][268] ========
        unsigned* As = dyn_u;
        unsigned* Bs = dyn_u + 64 * 68;
        const int s0 = blockIdx.x * 256;
        const float* Ag = KT + (size_t)bh * DK * S;
        const __half* Bg = scT + (size_t)bh * S * S + s0;
        const int nw = w * 32;
        inv[tid] = rinv[bh * S + s0 + tid];
        const int kq6 = tid & 15, ahalf = kq6 >> 3, kq = kq6 & 7;
        const int akc = ahalf * 32 + kq * 4;
        const int abkp = ahalf * 32 + (kq >> 1) * 8 + (kq & 1);
        __syncthreads();
        float c[16][4] = {};
        for (int k0 = 0; k0 < S; k0 += 64) {
            #pragma unroll
            for (int it = 0; it < 4; it++) {   // A = KT 64x64
                int m = (tid >> 4) + it * 16;
                float4 v = *(const float4*)(Ag + (size_t)m * S + k0 + akc);
                unsigned* dst = &As[m * 68 + abkp];
                dst[0] = tf32c(v.x); dst[2] = tf32c(v.y); dst[4] = tf32c(v.z); dst[6] = tf32c(v.w);
            }
            #pragma unroll
            for (int it = 0; it < 16; it++) {  // B = exp(scores)*inv  64x256
                int kr6 = (tid >> 6) + it * 4;
                int row = (kr6 >> 5) * 32 + kperm(kr6 & 31);
                int nc = (tid & 63) * 4;
                uint2 uv = *(const uint2*)(Bg + (size_t)(k0 + kr6) * S + nc);
                float2 fa = __half22float2(*(const __half2*)&uv.x);
                float2 fb = __half22float2(*(const __half2*)&uv.y);
                uint4 u;
                u.x = tf32c(__expf(fa.x) * inv[nc + 0]);
                u.y = tf32c(__expf(fa.y) * inv[nc + 1]);
                u.z = tf32c(__expf(fb.x) * inv[nc + 2]);
                u.w = tf32c(__expf(fb.y) * inv[nc + 3]);
                *(uint4*)&Bs[row * 268 + nc] = u;
            }
            __syncthreads();
            #pragma unroll
            for (int ks = 0; ks < 8; ks++) {
                const int kb = ((ks >> 2) << 5) + ((ks & 3) << 3) + 2 * tq;
                unsigned a[4][4], bf[4][2];
                #pragma unroll
                for (int i = 0; i < 4; i++) {
                    int r = 16 * i + g;
                    uint2 x = *(const uint2*)&As[r * 68 + kb];
                    uint2 y = *(const uint2*)&As[(r + 8) * 68 + kb];
                    a[i][0] = x.x; a[i][1] = y.x; a[i][2] = x.y; a[i][3] = y.y;
                }
                #pragma unroll
                for (int j = 0; j < 4; j++) {
                    int col = nw + 8 * j + g;
                    bf[j][0] = Bs[kb * 268 + col];
                    bf[j][1] = Bs[(kb + 1) * 268 + col];
                }
                #pragma unroll
                for (int i = 0; i < 4; i++)
                    #pragma unroll
                    for (int j = 0; j < 4; j++) mma8(c[i * 4 + j], a[i], bf[j]);
            }
            __syncthreads();
        }
        #pragma unroll
        for (int i = 0; i < 4; i++) {
            int d = 16 * i + g;
            #pragma unroll
            for (int j = 0; j < 4; j++) {
                int s = s0 + nw + 8 * j + 2 * tq;
                float* cc = c[i * 4 + j];
                size_t a0 = (size_t)(b * S + s) * D + h * DK + d;
                C1[a0]         = cc[0];
                C1[a0 + D]     = cc[1];
                C1[a0 + 8]     = cc[2];
                C1[a0 + D + 8] = cc[3];
            }
        }
    } else {
        // ======== ctx2: m=t(256), n=d(64), k=s. As [256][68], Bs [64][68] ========
        unsigned* As = dyn_u;
        unsigned* Bs = dyn_u + 256 * 68;
        const int t0 = blockIdx.x * 256;
        const __half* Ag = scT + ((size_t)bh * S + t0) * S;
        const float* Bg = Q + (size_t)b * S * D + h * DK;
        const int mw = (w >> 1) * 64, nw = (w & 1) * 32;
        inv[tid] = cinv[bh * S + t0 + tid];
        const int kq6 = tid & 15, ahalf = kq6 >> 3, kq = kq6 & 7;
        const int akc = ahalf * 32 + kq * 4;
        const int abkp = ahalf * 32 + (kq >> 1) * 8 + (kq & 1);
        __syncthreads();
        float c[16][4] = {};
        for (int k0 = 0; k0 < S; k0 += 64) {
            #pragma unroll
            for (int it = 0; it < 16; it++) {  // A = exp(scores)*inv  256x64
                int m = (tid >> 4) + it * 16;
                uint2 uv = *(const uint2*)(Ag + (size_t)m * S + k0 + akc);
                float2 fa = __half22float2(*(const __half2*)&uv.x);
                float2 fb = __half22float2(*(const __half2*)&uv.y);
                float ci = inv[m];
                unsigned* dst = &As[m * 68 + abkp];
                dst[0] = tf32c(__expf(fa.x) * ci);
                dst[2] = tf32c(__expf(fa.y) * ci);
                dst[4] = tf32c(__expf(fb.x) * ci);
                dst[6] = tf32c(__expf(fb.y) * ci);
            }
            #pragma unroll
            for (int it = 0; it < 4; it++) {   // B = Q 64x64
                int kr6 = (tid >> 4) + it * 16;
                int row = (kr6 >> 5) * 32 + kperm(kr6 & 31);
                int nc = (tid & 15) * 4;
                float4 v = *(const float4*)(Bg + (size_t)(k0 + kr6) * D + nc);
                uint4 u; u.x = tf32c(v.x); u.y = tf32c(v.y); u.z = tf32c(v.z); u.w = tf32c(v.w);
                *(uint4*)&Bs[row * 68 + nc] = u;
            }
            __syncthreads();
            #pragma unroll
            for (int ks = 0; ks < 8; ks++) {
                const int kb = ((ks >> 2) << 5) + ((ks & 3) << 3) + 2 * tq;
                unsigned a[4][4], bf[2][2];
                #pragma unroll
                for (int i = 0; i < 4; i++) {
                    int r = mw + 16 * i + g;
                    uint2 x = *(const uint2*)&As[r * 68 + kb];
                    uint2 y = *(const uint2*)&As[(r + 8) * 68 + kb];
                    a[i][0] = x.x; a[i][1] = y.x; a[i][2] = x.y; a[i][3] = y.y;
                }
                #pragma unroll
                for (int j = 0; j < 4; j++) {
                    int col = nw + 8 * j + g;
                    bf[j & 1][0] = Bs[kb * 68 + col];
                    bf[j & 1][1] = Bs[(kb + 1) * 68 + col];
                    #pragma unroll
                    for (int i = 0; i < 4; i++) mma8(c[i * 4 + j], a[i], bf[j & 1]);
                }
            }
            __syncthreads();
        }
        #pragma unroll
        for (int i = 0; i < 4; i++) {
            int t = t0 + mw + 16 * i + g;
            #pragma unroll
            for (int j = 0; j < 4; j++) {
                int dcol = nw + 8 * j + 2 * tq;
                float* cc = c[i * 4 + j];
                size_t a0 = (size_t)(b * S + t) * D + h * DK + dcol;
                *(float2*)(C2 + a0)                 = make_float2(cc[0], cc[1]);
                *(float2*)(C2 + a0 + (size_t)8 * D) = make_float2(cc[2], cc[3]);
            }
        }
    }
}

// ---------------- batched LayerNorm over last dim (768) ----------------
__global__ void ln_kernel(const float* __restrict__ x,
                          const float* __restrict__ g1, const float* __restrict__ b1,
                          const float* __restrict__ g2, const float* __restrict__ b2,
                          float* __restrict__ out) {
    int row = blockIdx.x, tid = threadIdx.x;
    const float* gg = (row < Bz * S) ? g1 : g2;
    const float* bb = (row < Bz * S) ? b1 : b2;
    const float* xr = x + (size_t)row * D;
    float v0 = xr[tid], v1 = xr[tid + 256], v2 = xr[tid + 512];
    float s = v0 + v1 + v2;
    __shared__ float red[8];
    #pragma unroll
    for (int o = 16; o; o >>= 1) s += __shfl_xor_sync(0xffffffffu, s, o);
    if ((tid & 31) == 0) red[tid >> 5] = s;
    __syncthreads();
    float tot = 0.f;
    #pragma unroll
    for (int i = 0; i < 8; i++) tot += red[i];
    float mu = tot * (1.0f / 768.0f);
    float d0 = v0 - mu, d1 = v1 - mu, d2 = v2 - mu;
    float q = d0 * d0 + d1 * d1 + d2 * d2;
    #pragma unroll
    for (int o = 16; o; o >>= 1) q += __shfl_xor_sync(0xffffffffu, q, o);
    __syncthreads();
    if ((tid & 31) == 0) red[tid >> 5] = q;
    __syncthreads();
    float var = 0.f;
    #pragma unroll
    for (int i = 0; i < 8; i++) var += red[i];
    var *= (1.0f / 768.0f);
    float rs = rsqrtf(var + 1e-5f);
    float* orow = out + (size_t)row * D;
    orow[tid]       = d0 * rs * gg[tid]       + bb[tid];
    orow[tid + 256] = d1 * rs * gg[tid + 256] + bb[tid + 256];
    orow[tid + 512] = d2 * rs * gg[tid + 512] + bb[tid + 512];
}

// ---------------- launch ----------------
extern "C" void kernel_launch(void* const* d_in, const int* in_sizes, int n_in,
                              void* d_out, int out_size) {
    const float* pro1 = (const float*)d_in[0];
    const float* pro2 = (const float*)d_in[1];
    const void*  mask = d_in[2];
    const float* W_Q  = (const float*)d_in[3];
    const float* W_K  = (const float*)d_in[4];
    const float* fc1  = (const float*)d_in[5];
    const float* g1   = (const float*)d_in[6];
    const float* b1   = (const float*)d_in[7];
    const float* g2   = (const float*)d_in[8];
    const float* b2   = (const float*)d_in[9];
    float* out = (float*)d_out;

    float *Qp, *Kp, *QTp, *KTp, *CX, *Tp, *CP, *RI, *CI;
    __half* Sp;
    cudaGetSymbolAddress((void**)&Qp, g_Q);
    cudaGetSymbolAddress((void**)&Kp, g_K);
    cudaGetSymbolAddress((void**)&QTp, g_QT);
    cudaGetSymbolAddress((void**)&KTp, g_KT);
    cudaGetSymbolAddress((void**)&Sp, g_sc);
    cudaGetSymbolAddress((void**)&CX, g_ctx);
    cudaGetSymbolAddress((void**)&Tp, g_t);
    cudaGetSymbolAddress((void**)&CP, g_cpart);
    cudaGetSymbolAddress((void**)&RI, g_rinv);
    cudaGetSymbolAddress((void**)&CI, g_cinv);

    cudaFuncSetAttribute(mm128_dual_kernel, cudaFuncAttributeMaxDynamicSharedMemorySize, MM_SMEM);
    cudaFuncSetAttribute(mm128_kernel, cudaFuncAttributeMaxDynamicSharedMemorySize, MM_SMEM);
    cudaFuncSetAttribute(scoresT_kernel, cudaFuncAttributeMaxDynamicSharedMemorySize, SC_SMEM);
    cudaFuncSetAttribute(ctx_kernel, cudaFuncAttributeMaxDynamicSharedMemorySize, CTX_SMEM);

    detect_mask_kernel<<<1, 256>>>((const unsigned int*)mask);

    mm128_dual_kernel<<<dim3(6, 32, 2), 256, MM_SMEM>>>(pro1, W_Q, Qp, pro2, W_K, Kp);

    tr_kernel<<<dim3(32, 2, 2 * BH), dim3(32, 8)>>>(Qp, QTp, Kp, KTp);

    scoresT_kernel<<<dim3(8, 8, BH), 256, SC_SMEM>>>(Kp, QTp, mask, Sp);

    sums_kernel<<<dim3(8, BH), 256>>>(Sp, CP, CI);
    rinv_kernel<<<dim3(4, BH), 256>>>(CP, RI);

    ctx_kernel<<<dim3(4, BH, 2), 256, CTX_SMEM>>>(KTp, Sp, Qp, RI, CI, CX, CX + (size_t)Bz * S * D);

    mm128_kernel<<<dim3(6, 64), 256, MM_SMEM>>>(CX, fc1, Tp);

    ln_kernel<<<2 * Bz * S, 256>>>(Tp, g1, b1, g2, b2, out);
}